// round 14
// baseline (speedup 1.0000x reference)
#include <cuda_runtime.h>

// Problem constants (match reference)
#define NUM_CH   5
#define CROP_LO  70      // D//2 - 16, D = 173
#define CROP_HI  101     // CROP_LO + 32 - 1
#define CROP_N   32
#define CUBES    5
#define LATO     11      // 2*CUBES+1
#define RES2     0.0625f // RES*RES

#define GROUP    256                 // threads per atom
#define APB      2                   // atoms per block
#define NTHREADS (GROUP * APB)       // 512

// Splat kernel: no smem, no barriers, no shuffles. Each 256-thread group owns
// one atom; every thread loads the atom's 5 scalars itself (warp-uniform LDG
// -> L1 broadcast), derives identically, and splats its <=6 cells with REDs.
// Zero-init is a preceding graph memset node (ordering via graph edge).
__global__ void __launch_bounds__(NTHREADS) splat_kernel(
    const float* __restrict__ coords,        // [B, N, 3]
    const int*   __restrict__ atoms_channel, // [B, N]
    const float* __restrict__ radius,        // [B, N]
    float* __restrict__ out,                 // [B, NUM_CH, 32, 32, 32]
    int n_per_batch, int n_atoms)
{
    const int tid   = threadIdx.x;
    const int group = tid >> 8;                    // 0..1
    const int gtid  = tid & (GROUP - 1);           // 0..255
    const int atom  = blockIdx.x * APB + group;
    if (atom >= n_atoms) return;
    const int b = atom / n_per_batch;

    // --- uniform scalar loads (all 5 issue independently, L1 broadcast) ---
    const float cx = coords[3 * atom + 0];
    const float cy = coords[3 * atom + 1];
    const float cz = coords[3 * atom + 2];
    const float r  = radius[atom];
    const int   ch = atoms_channel[atom];

    // scaled = (c + BOX)/RES + (CUBES+1); /0.25 == *4 exactly
    const float sx = (cx + 20.0f) * 4.0f + 6.0f;
    const float sy = (cy + 20.0f) * 4.0f + 6.0f;
    const float sz = (cz + 20.0f) * 4.0f + 6.0f;
    const int bx = (int)floorf(sx) - CUBES;
    const int by = (int)floorf(sy) - CUBES;
    const int bz = (int)floorf(sz) - CUBES;

    // clip splat box against crop window [CROP_LO, CROP_HI]
    const int x0 = max(0, CROP_LO - bx), x1 = min(LATO - 1, CROP_HI - bx);
    const int y0 = max(0, CROP_LO - by), y1 = min(LATO - 1, CROP_HI - by);
    const int z0 = max(0, CROP_LO - bz), z1 = min(LATO - 1, CROP_HI - bz);
    const int nx = x1 - x0 + 1, ny = y1 - y0 + 1, nz = z1 - z0 + 1;
    if (nx <= 0 || ny <= 0 || nz <= 0) return;     // splat misses the crop

    const float coef = 0.5f * RES2 / (r * r);
    const float fx = sx - (float)(bx + x0) - 0.5f;
    const float fy = sy - (float)(by + y0) - 0.5f;
    const float fz = sz - (float)(bz + z0) - 0.5f;

    const int nyz  = ny * nz;
    const int ntot = nx * nyz;                     // <= 1331
    const float rnyz = 1.0f / (float)nyz;
    const float rnz  = 1.0f / (float)nz;

    float* __restrict__ p = out
        + (size_t)(b * NUM_CH + ch) * (CROP_N * CROP_N * CROP_N)
        + ((bx + x0 - CROP_LO) * CROP_N + (by + y0 - CROP_LO)) * CROP_N
        + (bz + z0 - CROP_LO);

    for (int k = gtid; k < ntot; k += GROUP) {     // <= 6 iterations
        // exact small-int division via fp32 (k < 1331, divisors <= 121)
        int ox  = (int)(((float)k + 0.5f) * rnyz);
        int rem = k - ox * nyz;
        int oy  = (int)(((float)rem + 0.5f) * rnz);
        int oz  = rem - oy * nz;
        float dx = fx - (float)ox;
        float dy = fy - (float)oy;
        float dz = fz - (float)oz;
        float d2 = fmaf(dx, dx, fmaf(dy, dy, dz * dz));
        float v  = __expf(-coef * d2);
        atomicAdd(&p[(ox * CROP_N + oy) * CROP_N + oz], v);
    }
}

extern "C" void kernel_launch(void* const* d_in, const int* in_sizes, int n_in,
                              void* d_out, int out_size) {
    const float* coords        = (const float*)d_in[0]; // [B,N,3]
    const int*   atoms_channel = (const int*)d_in[1];   // [B,N]
    const float* radius        = (const float*)d_in[2]; // [B,N]
    float* out = (float*)d_out;

    int n_atoms = in_sizes[1];                               // B*N = 512
    int B = out_size / (NUM_CH * CROP_N * CROP_N * CROP_N);  // 8
    int n_per_batch = n_atoms / B;                           // 64

    // Zero output via graph memset node (ordering via graph edge)
    cudaMemsetAsync(out, 0, (size_t)out_size * sizeof(float));

    // 2 atoms per block -> 256 blocks x 512 threads
    int blocks = (n_atoms + APB - 1) / APB;
    splat_kernel<<<blocks, NTHREADS>>>(coords, atoms_channel, radius, out,
                                       n_per_batch, n_atoms);
}